// round 2
// baseline (speedup 1.0000x reference)
#include <cuda_runtime.h>

// XdGate on site INDEX=3 of an L=8 qutrit (D=3) state vector, N = 3^8 = 6561.
//
// U = I x I x I x M x I x I x I x I with M|i> = |(3-i) mod 3> — a pure
// permutation on the site-3 trit (stride 3^4 = 81):
//   t=0 -> delta 0, t=1 -> delta +81, t=2 -> delta -81 (element offsets).
//
// Launch-overhead bound. R2: float4 stores (contiguous out), 4 scalar gathers
// per thread (MLP=4), 7 blocks x 256 threads instead of 26 x 256.

static constexpr int N_STATE = 6561;   // 3^8
static constexpr int STRIDE  = 81;     // 3^4
static constexpr int N_VEC   = N_STATE / 4;  // 1640 float4 groups; 1 tail elem

__device__ __forceinline__ int src_of(int idx) {
    int t = (idx / STRIDE) % 3;
    // delta: t=0 -> 0, t=1 -> +STRIDE, t=2 -> -STRIDE
    int delta = (t == 1) ? STRIDE : ((t == 2) ? -STRIDE : 0);
    return idx + delta;
}

__global__ __launch_bounds__(256) void xd_gate_kernel(
    const float* __restrict__ x, float* __restrict__ out) {
    int v = blockIdx.x * blockDim.x + threadIdx.x;

    if (v < N_VEC) {
        int idx = v * 4;
        // 4 independent gathers — issued back-to-back, latencies overlap.
        float a = x[src_of(idx + 0)];
        float b = x[src_of(idx + 1)];
        float c = x[src_of(idx + 2)];
        float d = x[src_of(idx + 3)];
        reinterpret_cast<float4*>(out)[v] = make_float4(a, b, c, d);
    } else if (v == N_VEC) {
        // tail: element 6560
        int idx = N_VEC * 4;
        out[idx] = x[src_of(idx)];
    }
}

extern "C" void kernel_launch(void* const* d_in, const int* in_sizes, int n_in,
                              void* d_out, int out_size) {
    const float* x = (const float*)d_in[0];   // [6561, 1] float32
    float* out = (float*)d_out;

    const int threads = 256;
    const int total = N_VEC + 1;              // 1641 threads
    const int blocks = (total + threads - 1) / threads;  // 7
    xd_gate_kernel<<<blocks, threads>>>(x, out);
}

// round 3
// speedup vs baseline: 1.2102x; 1.2102x over previous
#include <cuda_runtime.h>

// XdGate on site INDEX=3 of an L=8 qutrit (D=3) state vector, N = 3^8 = 6561.
//
// U = I x I x I x M x I x I x I x I with M|i> = |(3-i) mod 3> — a pure
// permutation of the site-3 trit (stride 3^4 = 81):
//   t=0 -> delta 0, t=1 -> +81, t=2 -> -81 (element offsets).
//
// Launch-overhead bound (~5us graph-replay floor; DRAM 0.1%, issue <8%).
// R3: exact grid cover 27 x 243 = 6561 -> no bounds guard, no tail;
// branchless delta; one scalar gather per thread (measured best structure).

static constexpr int STRIDE = 81;   // 3^4

__global__ __launch_bounds__(243) void xd_gate_kernel(
    const float* __restrict__ x, float* __restrict__ out) {
    int idx = blockIdx.x * 243 + threadIdx.x;   // exact cover of [0, 6561)

    int t = (idx / STRIDE) % 3;
    // delta multiplier: t=0 -> 0, t=1 -> +1, t=2 -> -1
    int d = (t == 1) - (t == 2);
    out[idx] = x[idx + d * STRIDE];
}

extern "C" void kernel_launch(void* const* d_in, const int* in_sizes, int n_in,
                              void* d_out, int out_size) {
    const float* x = (const float*)d_in[0];   // [6561, 1] float32
    // d_in[1] is M [3,3] — permutation baked in.
    float* out = (float*)d_out;

    xd_gate_kernel<<<27, 243>>>(x, out);      // 27 * 243 = 6561 exactly
}